// round 5
// baseline (speedup 1.0000x reference)
#include <cuda_runtime.h>
#include <math_constants.h>

// Problem constants
#define BB 2
#define CIN 3
#define HH 32
#define WW 32
#define CM 32      // mid channels
#define HQ 16      // mid spatial
#define CO 64      // out channels
#define HP 8       // out spatial
#define NP 64      // HP*HP
#define NI 1024    // HH*WW
#define NE 512     // num embeddings

#define NBLK 128   // persistent grid: <= SM count, all resident
#define NTHR 256

// Scratch in device globals (no allocations allowed)
__device__ float g_xw1[BB][HQ][HQ][16][CM];  // per-tap conv1 partials, [k1][m]
__device__ float g_y1[BB][HQ][HQ][CM];       // relu(conv1)
__device__ float g_y[BB][NP][CO];            // relu(conv2)
__device__ float g_rm[BB][NP][CO];           // 2*(y - q(y)) * mask2
__device__ float g_v[BB][NP][16][16];        // [k2][k1]
__device__ float g_ymask[BB][NP][CO];
__device__ float g_w2t[16][CM][CO];          // w2 transposed: [k2][m][o]
__device__ float g_KmT[CO][NE];              // K transposed: [o][k]
__device__ int   g_sel[BB][NI];

// Software grid barrier state (replay-safe: count self-resets, gen is monotonic)
__device__ unsigned int g_bar_count = 0;
__device__ unsigned int g_bar_gen = 0;

__device__ __forceinline__ void grid_barrier(unsigned int& gen) {
    __syncthreads();
    if (threadIdx.x == 0) {
        __threadfence();
        unsigned int prev = atomicAdd(&g_bar_count, 1);
        if (prev == NBLK - 1) {
            g_bar_count = 0;
            __threadfence();
            atomicAdd(&g_bar_gen, 1);
        } else {
            unsigned int cur;
            do {
                asm volatile("ld.acquire.gpu.u32 %0, [%1];" : "=r"(cur) : "l"(&g_bar_gen));
                if (cur != gen) break;
                __nanosleep(32);
            } while (true);
        }
        gen++;
    }
    __syncthreads();
}

// Shuffle-based block reductions over 256 threads
__device__ __forceinline__ float blockMax256(float v, float* red8, int t) {
#pragma unroll
    for (int off = 16; off > 0; off >>= 1)
        v = fmaxf(v, __shfl_xor_sync(0xffffffffu, v, off));
    if ((t & 31) == 0) red8[t >> 5] = v;
    __syncthreads();
    if (t < 32) {
        float w = (t < 8) ? red8[t] : -CUDART_INF_F;
#pragma unroll
        for (int off = 4; off > 0; off >>= 1)
            w = fmaxf(w, __shfl_xor_sync(0xffffffffu, w, off));
        if (t == 0) red8[0] = w;
    }
    __syncthreads();
    return red8[0];
}
__device__ __forceinline__ float blockSum256(float v, float* red8, int t) {
#pragma unroll
    for (int off = 16; off > 0; off >>= 1)
        v += __shfl_xor_sync(0xffffffffu, v, off);
    if ((t & 31) == 0) red8[t >> 5] = v;
    __syncthreads();
    if (t < 32) {
        float w = (t < 8) ? red8[t] : 0.f;
#pragma unroll
        for (int off = 4; off > 0; off >>= 1)
            w += __shfl_xor_sync(0xffffffffu, w, off);
        if (t == 0) red8[0] = w;
    }
    __syncthreads();
    return red8[0];
}

// Per-phase shared memory layouts, overlaid in a union
struct SmBC {
    float sy1[16][CM];
    float yv[CO];
    float wexp[NE];
    float redA[8];
    float redB[8];
    float red2[4][CO];
};
struct SmDE {
    float r[CO];
    float w1s[CM][16];
    float sm[CM][16];
    float sw[16][512];
};
struct SmF { float sv[2][64][16]; };
struct SmG { float am_s[4][4][32]; int selp[4]; };
union SmAll {
    SmBC bc;
    SmDE de;
    SmF f;
    SmG g;
};

__global__ void __launch_bounds__(NTHR, 1)
megakernel(const float* __restrict__ x, const float* __restrict__ w1,
           const float* __restrict__ b1, const float* __restrict__ w2,
           const float* __restrict__ b2, const float* __restrict__ Km,
           const float* __restrict__ Vm, float* __restrict__ out) {
    __shared__ SmAll smu;
    int t = threadIdx.x;
    int blk = blockIdx.x;
    unsigned int gen = 0;
    if (t == 0) {
        asm volatile("ld.acquire.gpu.u32 %0, [%1];" : "=r"(gen) : "l"(&g_bar_gen));
    }

    // ===================== Phase A: conv1 partials, transposes, zero ymask ====
    {
        int gid = blk * NTHR + t;  // 0..32767
        {
            int k2 = gid >> 11, m = (gid >> 6) & 31, o = gid & 63;
            g_w2t[k2][m][o] = w2[(o * CM + m) * 16 + k2];
            int o2 = gid >> 9, kk = gid & 511;
            g_KmT[o2][kk] = Km[kk * CO + o2];
        }
        if (gid < BB * NP * CO) (&g_ymask[0][0][0])[gid] = 0.f;
        if (gid < BB * HQ * HQ * CM) {
            int m = gid & 31;
            int site = gid >> 5;
            int b = site >> 8;
            int q = site & 255;
            int qh = q >> 4, qw = q & 15;
            float acc = b1[m];
#pragma unroll
            for (int k = 0; k < 16; k++) {
                int kh = k >> 2, kw = k & 3;
                int xh = 2 * qh - 1 + kh, xw = 2 * qw - 1 + kw;
                float vv = 0.f;
                if (xh >= 0 && xh < HH && xw >= 0 && xw < WW) {
#pragma unroll
                    for (int c = 0; c < CIN; c++)
                        vv += w1[(m * CIN + c) * 16 + k] *
                              x[((b * CIN + c) * HH + xh) * WW + xw];
                }
                g_xw1[b][qh][qw][k][m] = vv;
                acc += vv;
            }
            g_y1[b][qh][qw][m] = fmaxf(acc, 0.f);
        }
    }
    grid_barrier(gen);

    // ===================== Phase BC: conv2 + relu + hopfield -> rm ============
    {
        int b = blk / NP, p = blk % NP;
        int ph = p / HP, pw = p % HP;
        for (int idx = t; idx < CM * 16; idx += NTHR) {
            int k = idx >> 5, m = idx & 31;
            int kh = k / 4, kw = k % 4;
            int qh = 2 * ph - 1 + kh, qw = 2 * pw - 1 + kw;
            float vv = 0.f;
            if (qh >= 0 && qh < HQ && qw >= 0 && qw < HQ) vv = g_y1[b][qh][qw][m];
            smu.bc.sy1[k][m] = vv;
        }
        __syncthreads();
        {
            int o = t & 63, q4 = t >> 6;
            float acc = 0.f;
#pragma unroll
            for (int mm = 0; mm < 8; mm++) {
                int m = q4 * 8 + mm;
#pragma unroll
                for (int k = 0; k < 16; k++)
                    acc += g_w2t[k][m][o] * smu.bc.sy1[k][m];
            }
            smu.bc.red2[q4][o] = acc;
        }
        __syncthreads();
        if (t < CO) {
            float acc = b2[t] + smu.bc.red2[0][t] + smu.bc.red2[1][t] +
                        smu.bc.red2[2][t] + smu.bc.red2[3][t];
            float yy = fmaxf(acc, 0.f);
            smu.bc.yv[t] = yy;
            g_y[b][p][t] = yy;
        }
        __syncthreads();
        float l[2];
        float lmax = -1e30f;
#pragma unroll
        for (int j = 0; j < 2; j++) {
            int k = t + 256 * j;
            float acc = 0.f;
#pragma unroll 8
            for (int o = 0; o < CO; o++) acc += g_KmT[o][k] * smu.bc.yv[o];
            l[j] = 0.125f * acc;
            lmax = fmaxf(lmax, l[j]);
        }
        lmax = blockMax256(lmax, smu.bc.redA, t);
        float ssum = 0.f;
#pragma unroll
        for (int j = 0; j < 2; j++) {
            float e = expf(l[j] - lmax);
            smu.bc.wexp[t + 256 * j] = e;
            ssum += e;
        }
        float tot = blockSum256(ssum, smu.bc.redB, t);
        float inv = 1.f / tot;
        __syncthreads();
        {
            int o = t & 63, q4 = t >> 6;
            float acc = 0.f;
            int k0 = q4 * 128;
#pragma unroll 8
            for (int kk = 0; kk < 128; kk++)
                acc += smu.bc.wexp[k0 + kk] * Vm[(k0 + kk) * CO + o];
            smu.bc.red2[q4][o] = acc;
        }
        __syncthreads();
        if (t < CO) {
            float e = (smu.bc.red2[0][t] + smu.bc.red2[1][t] + smu.bc.red2[2][t] +
                       smu.bc.red2[3][t]) * inv;
            float yy = smu.bc.yv[t];
            g_rm[b][p][t] = (yy > 0.f) ? 2.f * (yy - e) : 0.f;
        }
    }
    grid_barrier(gen);

    // ===================== Phase DE: s (smem) then v ==========================
    {
        int b = blk / NP, p = blk % NP;
        int ph = p / HP, pw = p % HP;
        if (t < CO) smu.de.r[t] = g_rm[b][p][t];
        for (int idx = t; idx < 512; idx += NTHR) {
            int m = idx / 16, k = idx % 16;
            float acc = 0.f;
#pragma unroll
            for (int c = 0; c < CIN; c++) acc += w1[(m * CIN + c) * 16 + k];
            smu.de.w1s[m][k] = acc;
        }
        __syncthreads();
        float accv0 = 0.f, accv1 = 0.f;
        for (int c = 0; c < 4; c++) {
#pragma unroll
            for (int j = 0; j < 16; j++) {
                smu.de.sw[j][t] = w2[(c * 16 + j) * 512 + t];
                smu.de.sw[j][t + 256] = w2[(c * 16 + j) * 512 + t + 256];
            }
            __syncthreads();
#pragma unroll
            for (int j = 0; j < 16; j++) {
                float rv = smu.de.r[c * 16 + j];
                accv0 += rv * smu.de.sw[j][t];
                accv1 += rv * smu.de.sw[j][t + 256];
            }
            __syncthreads();
        }
#pragma unroll
        for (int half = 0; half < 2; half++) {
            int t2 = t + half * 256;
            float acc = half ? accv1 : accv0;
            int m = t2 / 16, k2 = t2 % 16;
            int kh = k2 / 4, kw = k2 % 4;
            int qh = 2 * ph - 1 + kh, qw = 2 * pw - 1 + kw;
            float sv = 0.f;
            if (qh >= 0 && qh < HQ && qw >= 0 && qw < HQ && g_y1[b][qh][qw][m] > 0.f)
                sv = acc;
            smu.de.sm[m][k2] = sv;
        }
        __syncthreads();
        {
            int k2 = t / 16, k1 = t % 16;
            float a2 = 0.f;
#pragma unroll 8
            for (int m = 0; m < CM; m++) a2 += smu.de.sm[m][k2] * smu.de.w1s[m][k1];
            g_v[b][p][k2][k1] = a2;
        }
    }
    grid_barrier(gen);

    // ===================== Phase F: argmin over p per pixel row ===============
    if (blk < BB * HH) {
        int b = blk / HH, ih = blk % HH;
        int qh0 = (ih + 1) >> 1;
        for (int idx = t; idx < 2 * 64 * 4; idx += NTHR) {
            int qc = idx >> 8;
            int rem = idx & 255;
            int p = rem >> 2, k2w = rem & 3;
            int qh = qh0 - qc;
            int ph = p >> 3;
            int k2h = qh - 2 * ph + 1;
            int k1h = ih + 1 - 2 * qh;
            float4 val = make_float4(0.f, 0.f, 0.f, 0.f);
            if (qh >= 0 && qh < HQ && k2h >= 0 && k2h <= 3)
                val = *(const float4*)&g_v[b][p][k2h * 4 + k2w][k1h * 4];
            *(float4*)&smu.f.sv[qc][p][k2w * 4] = val;
        }
        __syncthreads();
        int iw = t >> 3, g = t & 7;
        int qw0 = (iw + 1) >> 1;
        float best = CUDART_INF_F;
        int bestp = 127;
        for (int pp = 0; pp < 8; pp++) {
            int p = g * 8 + pp;
            int ph = p >> 3, pw = p & 7;
            float e = 0.f;
#pragma unroll
            for (int qc = 0; qc < 2; qc++) {
                int qh = qh0 - qc;
                int k2h = qh - 2 * ph + 1;
                if (qh < 0 || qh >= HQ || k2h < 0 || k2h > 3) continue;
#pragma unroll
                for (int dqw = 0; dqw < 2; dqw++) {
                    int qw = qw0 - dqw;
                    int k2w = qw - 2 * pw + 1;
                    if (qw < 0 || qw >= HQ || k2w < 0 || k2w > 3) continue;
                    e += smu.f.sv[qc][p][k2w * 4 + (iw + 1 - 2 * qw)];
                }
            }
            if (e < best) { best = e; bestp = p; }
        }
#pragma unroll
        for (int off = 4; off > 0; off >>= 1) {
            float eo = __shfl_down_sync(0xffffffffu, best, off, 8);
            int po = __shfl_down_sync(0xffffffffu, bestp, off, 8);
            if (eo < best || (eo == best && po < bestp)) { best = eo; bestp = po; }
        }
        if (g == 0) g_sel[b][ih * WW + iw] = bestp;
    }
    grid_barrier(gen);

    // ===================== Phase G: scatter contrib into ymask ================
    {
        int g4 = t >> 6, o = t & 63;
        for (int iter = 0; iter < 4; iter++) {
            __syncthreads();
            int pix = iter * (NBLK * 4) + blk * 4 + g4;  // 0..2047
            int b = pix >> 10;
            int i = pix & 1023;
            int ih = i >> 5, iw = i & 31;
            int qh0 = (ih + 1) >> 1, qw0 = (iw + 1) >> 1;
            if (o == 0) smu.g.selp[g4] = g_sel[b][i];
            __syncthreads();
            int p = smu.g.selp[g4];
            int ph = p >> 3, pw = p & 7;
#pragma unroll
            for (int rep = 0; rep < 2; rep++) {
                int e2 = rep * 64 + o;
                int qc = e2 >> 5, m = e2 & 31;
                int qh = qh0 - (qc >> 1), qw = qw0 - (qc & 1);
                float vv = 0.f;
                if (qh >= 0 && qh < HQ && qw >= 0 && qw < HQ) {
                    int k2h = qh - 2 * ph + 1, k2w = qw - 2 * pw + 1;
                    if (k2h >= 0 && k2h <= 3 && k2w >= 0 && k2w <= 3) {
                        if (g_y1[b][qh][qw][m] > 0.f) {
                            int k1 = (ih + 1 - 2 * qh) * 4 + (iw + 1 - 2 * qw);
                            vv = g_xw1[b][qh][qw][k1][m];
                        }
                    }
                }
                smu.g.am_s[g4][qc][m] = vv;
            }
            __syncthreads();
            float yy = g_y[b][p][o];
            if (yy > 0.f) {
                float acc = 0.f;
#pragma unroll
                for (int qc = 0; qc < 4; qc++) {
                    int qh = qh0 - (qc >> 1), qw = qw0 - (qc & 1);
                    if (qh < 0 || qh >= HQ || qw < 0 || qw >= HQ) continue;
                    int k2h = qh - 2 * ph + 1, k2w = qw - 2 * pw + 1;
                    if (k2h < 0 || k2h > 3 || k2w < 0 || k2w > 3) continue;
                    int k2 = k2h * 4 + k2w;
#pragma unroll 8
                    for (int m = 0; m < CM; m++)
                        acc += g_w2t[k2][m][o] * smu.g.am_s[g4][qc][m];
                }
                if (acc != 0.f) atomicAdd(&g_ymask[b][p][o], acc);
            }
        }
    }
    grid_barrier(gen);

    // ===================== Phase H: final hopfield -> out =====================
    {
        int b = blk / NP, p = blk % NP;
        if (t < CO) smu.bc.yv[t] = g_ymask[b][p][t];
        __syncthreads();
        float l[2];
        float lmax = -1e30f;
#pragma unroll
        for (int j = 0; j < 2; j++) {
            int k = t + 256 * j;
            float acc = 0.f;
#pragma unroll 8
            for (int o = 0; o < CO; o++) acc += g_KmT[o][k] * smu.bc.yv[o];
            l[j] = 0.125f * acc;
            lmax = fmaxf(lmax, l[j]);
        }
        lmax = blockMax256(lmax, smu.bc.redA, t);
        float ssum = 0.f;
#pragma unroll
        for (int j = 0; j < 2; j++) {
            float e = expf(l[j] - lmax);
            smu.bc.wexp[t + 256 * j] = e;
            ssum += e;
        }
        float tot = blockSum256(ssum, smu.bc.redB, t);
        float inv = 1.f / tot;
        __syncthreads();
        {
            int o = t & 63, q4 = t >> 6;
            float acc = 0.f;
            int k0 = q4 * 128;
#pragma unroll 8
            for (int kk = 0; kk < 128; kk++)
                acc += smu.bc.wexp[k0 + kk] * Vm[(k0 + kk) * CO + o];
            smu.bc.red2[q4][o] = acc;
        }
        __syncthreads();
        if (t < CO) {
            float acc = (smu.bc.red2[0][t] + smu.bc.red2[1][t] + smu.bc.red2[2][t] +
                         smu.bc.red2[3][t]) * inv;
            out[(b * CO + t) * NP + p] = acc;
        }
    }
}

// ---------------------------------------------------------------------------
extern "C" void kernel_launch(void* const* d_in, const int* in_sizes, int n_in,
                              void* d_out, int out_size) {
    const float* x  = (const float*)d_in[0];  // (2,3,32,32)
    const float* w1 = (const float*)d_in[1];  // (32,3,4,4)
    const float* b1 = (const float*)d_in[2];  // (32,)
    const float* w2 = (const float*)d_in[3];  // (64,32,4,4)
    const float* b2 = (const float*)d_in[4];  // (64,)
    const float* Km = (const float*)d_in[5];  // (512,64)
    const float* Vm = (const float*)d_in[6];  // (512,64)
    float* out = (float*)d_out;               // (2,64,8,8)

    megakernel<<<NBLK, NTHR>>>(x, w1, b1, w2, b2, Km, Vm, out);
}

// round 6
// speedup vs baseline: 1.4356x; 1.4356x over previous
#include <cuda_runtime.h>
#include <math_constants.h>

// Problem constants
#define BB 2
#define CIN 3
#define HH 32
#define WW 32
#define CM 32      // mid channels
#define HQ 16      // mid spatial
#define CO 64      // out channels
#define HP 8       // out spatial
#define NP 64      // HP*HP
#define NI 1024    // HH*WW
#define NE 512     // num embeddings

// Scratch in device globals (no allocations allowed)
__device__ float g_xw1[BB][HQ][HQ][16][CM];  // per-tap conv1 partials, [k1][m]
__device__ float g_y1[BB][HQ][HQ][CM];       // relu(conv1)
__device__ float g_y[BB][NP][CO];            // relu(conv2)
__device__ float g_v[BB][NP][16][16];        // [k2][k1]
__device__ float g_ymask[BB][NP][CO];
__device__ float g_w2t[16][CM][CO];          // w2 transposed: [k2][m][o]
__device__ float g_KmT[CO][NE];              // K transposed: [o][k]

// ---------------------------------------------------------------------------
// Shuffle-based block reductions over 256 threads
__device__ __forceinline__ float blockMax256(float v, float* red8, int t) {
#pragma unroll
    for (int off = 16; off > 0; off >>= 1)
        v = fmaxf(v, __shfl_xor_sync(0xffffffffu, v, off));
    if ((t & 31) == 0) red8[t >> 5] = v;
    __syncthreads();
    if (t < 32) {
        float w = (t < 8) ? red8[t] : -CUDART_INF_F;
#pragma unroll
        for (int off = 4; off > 0; off >>= 1)
            w = fmaxf(w, __shfl_xor_sync(0xffffffffu, w, off));
        if (t == 0) red8[0] = w;
    }
    __syncthreads();
    return red8[0];
}
__device__ __forceinline__ float blockSum256(float v, float* red8, int t) {
#pragma unroll
    for (int off = 16; off > 0; off >>= 1)
        v += __shfl_xor_sync(0xffffffffu, v, off);
    if ((t & 31) == 0) red8[t >> 5] = v;
    __syncthreads();
    if (t < 32) {
        float w = (t < 8) ? red8[t] : 0.f;
#pragma unroll
        for (int off = 4; off > 0; off >>= 1)
            w += __shfl_xor_sync(0xffffffffu, w, off);
        if (t == 0) red8[0] = w;
    }
    __syncthreads();
    return red8[0];
}

// ---------------------------------------------------------------------------
// Kernel A: conv1 per-tap partials + relu(conv1); transposes; zero ymask
// grid = 128 blocks, 256 threads (one thread per (site, m) for conv part)
__global__ void __launch_bounds__(256, 1)
kA(const float* __restrict__ x, const float* __restrict__ w1,
   const float* __restrict__ b1, const float* __restrict__ w2,
   const float* __restrict__ Km) {
    int gid = blockIdx.x * 256 + threadIdx.x;  // 0..32767
    {
        int k2 = gid >> 11, m = (gid >> 6) & 31, o = gid & 63;
        g_w2t[k2][m][o] = w2[(o * CM + m) * 16 + k2];
        int o2 = gid >> 9, kk = gid & 511;
        g_KmT[o2][kk] = Km[kk * CO + o2];
    }
    if (gid < BB * NP * CO) (&g_ymask[0][0][0])[gid] = 0.f;
    if (gid < BB * HQ * HQ * CM) {
        int m = gid & 31;
        int site = gid >> 5;
        int b = site >> 8;
        int q = site & 255;
        int qh = q >> 4, qw = q & 15;
        float acc = b1[m];
#pragma unroll
        for (int k = 0; k < 16; k++) {
            int kh = k >> 2, kw = k & 3;
            int xh = 2 * qh - 1 + kh, xw = 2 * qw - 1 + kw;
            float vv = 0.f;
            if (xh >= 0 && xh < HH && xw >= 0 && xw < WW) {
#pragma unroll
                for (int c = 0; c < CIN; c++)
                    vv += w1[(m * CIN + c) * 16 + k] *
                          x[((b * CIN + c) * HH + xh) * WW + xw];
            }
            g_xw1[b][qh][qw][k][m] = vv;
            acc += vv;
        }
        g_y1[b][qh][qw][m] = fmaxf(acc, 0.f);
    }
}

// ---------------------------------------------------------------------------
// Kernel BCDE: conv2 + relu + hopfield -> rm (smem), then s -> v, per (b,p)
// grid = BB*NP = 128 blocks, 256 threads
struct SmBC {
    float sy1[16][CM];
    float yv[CO];
    float wexp[NE];
    float redA[8];
    float redB[8];
    float red2[4][CO];
};
struct SmDE {
    float w1s[CM][16];
    float sm[CM][16];
    float sw[16][512];
};
union SmBCDE { SmBC bc; SmDE de; };

__global__ void __launch_bounds__(256, 1)
kBCDE(const float* __restrict__ w1, const float* __restrict__ w2,
      const float* __restrict__ b2, const float* __restrict__ Vm) {
    __shared__ SmBCDE smu;
    __shared__ float rm_s[CO];
    int blk = blockIdx.x;
    int b = blk / NP, p = blk % NP;
    int ph = p / HP, pw = p % HP;
    int t = threadIdx.x;

    // ---- BC: conv2 + relu + hopfield residual ----
    for (int idx = t; idx < CM * 16; idx += 256) {
        int k = idx >> 5, m = idx & 31;
        int kh = k / 4, kw = k % 4;
        int qh = 2 * ph - 1 + kh, qw = 2 * pw - 1 + kw;
        float vv = 0.f;
        if (qh >= 0 && qh < HQ && qw >= 0 && qw < HQ) vv = g_y1[b][qh][qw][m];
        smu.bc.sy1[k][m] = vv;
    }
    __syncthreads();
    {
        int o = t & 63, q4 = t >> 6;
        float acc = 0.f;
#pragma unroll
        for (int mm = 0; mm < 8; mm++) {
            int m = q4 * 8 + mm;
#pragma unroll
            for (int k = 0; k < 16; k++)
                acc += g_w2t[k][m][o] * smu.bc.sy1[k][m];
        }
        smu.bc.red2[q4][o] = acc;
    }
    __syncthreads();
    if (t < CO) {
        float acc = b2[t] + smu.bc.red2[0][t] + smu.bc.red2[1][t] +
                    smu.bc.red2[2][t] + smu.bc.red2[3][t];
        float yy = fmaxf(acc, 0.f);
        smu.bc.yv[t] = yy;
        g_y[b][p][t] = yy;
    }
    __syncthreads();
    float l[2];
    float lmax = -1e30f;
#pragma unroll
    for (int j = 0; j < 2; j++) {
        int k = t + 256 * j;
        float acc = 0.f;
#pragma unroll 8
        for (int o = 0; o < CO; o++) acc += g_KmT[o][k] * smu.bc.yv[o];
        l[j] = 0.125f * acc;
        lmax = fmaxf(lmax, l[j]);
    }
    lmax = blockMax256(lmax, smu.bc.redA, t);
    float ssum = 0.f;
#pragma unroll
    for (int j = 0; j < 2; j++) {
        float e = expf(l[j] - lmax);
        smu.bc.wexp[t + 256 * j] = e;
        ssum += e;
    }
    float tot = blockSum256(ssum, smu.bc.redB, t);
    float inv = 1.f / tot;
    __syncthreads();
    {
        int o = t & 63, q4 = t >> 6;
        float acc = 0.f;
        int k0 = q4 * 128;
#pragma unroll 8
        for (int kk = 0; kk < 128; kk++)
            acc += smu.bc.wexp[k0 + kk] * Vm[(k0 + kk) * CO + o];
        smu.bc.red2[q4][o] = acc;
    }
    __syncthreads();
    if (t < CO) {
        float e = (smu.bc.red2[0][t] + smu.bc.red2[1][t] + smu.bc.red2[2][t] +
                   smu.bc.red2[3][t]) * inv;
        float yy = smu.bc.yv[t];
        rm_s[t] = (yy > 0.f) ? 2.f * (yy - e) : 0.f;
    }
    __syncthreads();   // BC smem reads done; safe to overwrite union with DE

    // ---- DE: s[m][k2] = sum_o rm[o]*w2[o][m][k2] (tiled), mask, then v ----
    for (int idx = t; idx < 512; idx += 256) {
        int m = idx / 16, k = idx % 16;
        float acc = 0.f;
#pragma unroll
        for (int c = 0; c < CIN; c++) acc += w1[(m * CIN + c) * 16 + k];
        smu.de.w1s[m][k] = acc;
    }
    __syncthreads();
    float accv0 = 0.f, accv1 = 0.f;
    for (int c = 0; c < 4; c++) {
#pragma unroll
        for (int j = 0; j < 16; j++) {
            smu.de.sw[j][t] = w2[(c * 16 + j) * 512 + t];
            smu.de.sw[j][t + 256] = w2[(c * 16 + j) * 512 + t + 256];
        }
        __syncthreads();
#pragma unroll
        for (int j = 0; j < 16; j++) {
            float rv = rm_s[c * 16 + j];
            accv0 += rv * smu.de.sw[j][t];
            accv1 += rv * smu.de.sw[j][t + 256];
        }
        __syncthreads();
    }
#pragma unroll
    for (int half = 0; half < 2; half++) {
        int t2 = t + half * 256;
        float acc = half ? accv1 : accv0;
        int m = t2 / 16, k2 = t2 % 16;
        int kh = k2 / 4, kw = k2 % 4;
        int qh = 2 * ph - 1 + kh, qw = 2 * pw - 1 + kw;
        float sv = 0.f;
        if (qh >= 0 && qh < HQ && qw >= 0 && qw < HQ && g_y1[b][qh][qw][m] > 0.f)
            sv = acc;
        smu.de.sm[m][k2] = sv;
    }
    __syncthreads();
    {
        int k2 = t / 16, k1 = t % 16;
        float a2 = 0.f;
#pragma unroll 8
        for (int m = 0; m < CM; m++) a2 += smu.de.sm[m][k2] * smu.de.w1s[m][k1];
        g_v[b][p][k2][k1] = a2;
    }
}

// ---------------------------------------------------------------------------
// Kernel FG: argmin + scatter, 4 pixels per block (all same row ih)
// grid = BB*NI/4 = 512 blocks, 256 threads
__global__ void __launch_bounds__(256, 1)
kFG() {
    __shared__ float am_s[4][4][32];
    __shared__ int selp[4];
    __shared__ float we_s[8];   // per-warp argmin partials (e)
    __shared__ int wp_s[8];     // per-warp argmin partials (p)
    int t = threadIdx.x;
    int g4 = t >> 6;            // pixel-in-block 0..3
    int pix0 = blockIdx.x * 4;  // first pixel of block
    int b0 = pix0 >> 10;
    int i0 = pix0 & 1023;
    int ih = i0 >> 5;           // same row for all 4 pixels
    int qh0 = (ih + 1) >> 1;

    // ---- argmin: thread t = g4*64 + p ----
    {
        int p = t & 63;
        int pixa = pix0 + g4;
        int ba = pixa >> 10;
        int ia = pixa & 1023;
        int iwa = ia & 31;
        int qw0a = (iwa + 1) >> 1;
        int pha = p >> 3, pwa = p & 7;
        float e = 0.f;
#pragma unroll
        for (int qc = 0; qc < 2; qc++) {
            int qh = qh0 - qc;
            int k2h = qh - 2 * pha + 1;
            if (qh < 0 || qh >= HQ || k2h < 0 || k2h > 3) continue;
            int k1h = ih + 1 - 2 * qh;
#pragma unroll
            for (int dqw = 0; dqw < 2; dqw++) {
                int qw = qw0a - dqw;
                int k2w = qw - 2 * pwa + 1;
                if (qw < 0 || qw >= HQ || k2w < 0 || k2w > 3) continue;
                e += g_v[ba][p][k2h * 4 + k2w][k1h * 4 + (iwa + 1 - 2 * qw)];
            }
        }
        // full-warp lexicographic (e,p) min — lanes hold p and p+32 halves
        float be = e;
        int bp = p;
#pragma unroll
        for (int off = 16; off > 0; off >>= 1) {
            float eo = __shfl_xor_sync(0xffffffffu, be, off);
            int po = __shfl_xor_sync(0xffffffffu, bp, off);
            if (eo < be || (eo == be && po < bp)) { be = eo; bp = po; }
        }
        if ((t & 31) == 0) { we_s[t >> 5] = be; wp_s[t >> 5] = bp; }
    }
    __syncthreads();
    if (t < 4) {
        float e0 = we_s[t * 2], e1 = we_s[t * 2 + 1];
        int p0 = wp_s[t * 2], p1 = wp_s[t * 2 + 1];
        selp[t] = (e1 < e0 || (e1 == e0 && p1 < p0)) ? p1 : p0;
    }
    __syncthreads();

    // ---- scatter contrib into ymask ----
    int o = t & 63;
    int pix = pix0 + g4;
    int b = pix >> 10;
    int i = pix & 1023;
    int iw = i & 31;
    int qw0 = (iw + 1) >> 1;
    int p = selp[g4];
    int ph = p >> 3, pw = p & 7;
#pragma unroll
    for (int rep = 0; rep < 2; rep++) {
        int e2 = rep * 64 + o;
        int qc = e2 >> 5, m = e2 & 31;
        int qh = qh0 - (qc >> 1), qw = qw0 - (qc & 1);
        float vv = 0.f;
        if (qh >= 0 && qh < HQ && qw >= 0 && qw < HQ) {
            int k2h = qh - 2 * ph + 1, k2w = qw - 2 * pw + 1;
            if (k2h >= 0 && k2h <= 3 && k2w >= 0 && k2w <= 3) {
                if (g_y1[b][qh][qw][m] > 0.f) {
                    int k1 = (ih + 1 - 2 * qh) * 4 + (iw + 1 - 2 * qw);
                    vv = g_xw1[b][qh][qw][k1][m];
                }
            }
        }
        am_s[g4][qc][m] = vv;
    }
    __syncthreads();
    float yy = g_y[b][p][o];
    if (yy > 0.f) {
        float acc = 0.f;
#pragma unroll
        for (int qc = 0; qc < 4; qc++) {
            int qh = qh0 - (qc >> 1), qw = qw0 - (qc & 1);
            if (qh < 0 || qh >= HQ || qw < 0 || qw >= HQ) continue;
            int k2h = qh - 2 * ph + 1, k2w = qw - 2 * pw + 1;
            if (k2h < 0 || k2h > 3 || k2w < 0 || k2w > 3) continue;
            int k2 = k2h * 4 + k2w;
#pragma unroll 8
            for (int m = 0; m < CM; m++)
                acc += g_w2t[k2][m][o] * am_s[g4][qc][m];
        }
        if (acc != 0.f) atomicAdd(&g_ymask[b][p][o], acc);
    }
}

// ---------------------------------------------------------------------------
// Kernel H: final hopfield on y_masked -> output (B, CO, HP, HP)
// grid = BB*NP = 128 blocks, 256 threads
__global__ void __launch_bounds__(256, 1)
kH(const float* __restrict__ Vm, float* __restrict__ out) {
    int blk = blockIdx.x;
    int b = blk / NP, p = blk % NP;
    __shared__ float yv[CO];
    __shared__ float wexp[NE];
    __shared__ float redA[8];
    __shared__ float redB[8];
    __shared__ float red2[4][CO];
    int t = threadIdx.x;
    if (t < CO) yv[t] = g_ymask[b][p][t];
    __syncthreads();
    float l[2];
    float lmax = -1e30f;
#pragma unroll
    for (int j = 0; j < 2; j++) {
        int k = t + 256 * j;
        float acc = 0.f;
#pragma unroll 8
        for (int o = 0; o < CO; o++) acc += g_KmT[o][k] * yv[o];
        l[j] = 0.125f * acc;
        lmax = fmaxf(lmax, l[j]);
    }
    lmax = blockMax256(lmax, redA, t);
    float ssum = 0.f;
#pragma unroll
    for (int j = 0; j < 2; j++) {
        float e = expf(l[j] - lmax);
        wexp[t + 256 * j] = e;
        ssum += e;
    }
    float tot = blockSum256(ssum, redB, t);
    float inv = 1.f / tot;
    __syncthreads();
    {
        int o = t & 63, q4 = t >> 6;
        float acc = 0.f;
        int k0 = q4 * 128;
#pragma unroll 8
        for (int kk = 0; kk < 128; kk++) acc += wexp[k0 + kk] * Vm[(k0 + kk) * CO + o];
        red2[q4][o] = acc;
    }
    __syncthreads();
    if (t < CO) {
        float acc = (red2[0][t] + red2[1][t] + red2[2][t] + red2[3][t]) * inv;
        out[(b * CO + t) * NP + p] = acc;
    }
}

// ---------------------------------------------------------------------------
extern "C" void kernel_launch(void* const* d_in, const int* in_sizes, int n_in,
                              void* d_out, int out_size) {
    const float* x  = (const float*)d_in[0];  // (2,3,32,32)
    const float* w1 = (const float*)d_in[1];  // (32,3,4,4)
    const float* b1 = (const float*)d_in[2];  // (32,)
    const float* w2 = (const float*)d_in[3];  // (64,32,4,4)
    const float* b2 = (const float*)d_in[4];  // (64,)
    const float* Km = (const float*)d_in[5];  // (512,64)
    const float* Vm = (const float*)d_in[6];  // (512,64)
    float* out = (float*)d_out;               // (2,64,8,8)

    kA<<<128, 256>>>(x, w1, b1, w2, Km);
    kBCDE<<<BB * NP, 256>>>(w1, w2, b2, Vm);
    kFG<<<BB * NI / 4, 256>>>();
    kH<<<BB * NP, 256>>>(Vm, out);
}